// round 11
// baseline (speedup 1.0000x reference)
#include <cuda_runtime.h>
#include <cstdint>

#define KA 13                 // k-stride (8 + 5 pad) -> <=2-way LDS/STS
#define AWS 420               // 32*KA + 4  (pooled-group panel stride, A)
#define BWS 836               // 64*KA + 4  (pooled-group panel stride, B)
#define ABUF (4*AWS)          // 1680 floats per A buffer (4 groups)
#define BBUF (4*BWS)          // 3344 floats per B buffer
#define OSM_ROW 321           // 64*5 + 1 (epilogue transpose row stride)
#define SMEM_FLOATS 10272     // max(2*(ABUF+BBUF)=10048, 32*321=10272)
#define SMEM_BYTES (SMEM_FLOATS*4)

#define CSTEP 16384           // +1 channel (floats)

__device__ __forceinline__ uint32_t f2tf32(float f) {
    uint32_t u; asm("cvt.rna.tf32.f32 %0, %1;" : "=r"(u) : "f"(f)); return u;
}
__device__ __forceinline__ void mma_tf32(float& d0, float& d1, float& d2, float& d3,
                                         uint32_t a0, uint32_t a1, uint32_t a2, uint32_t a3,
                                         uint32_t b0, uint32_t b1) {
    asm("mma.sync.aligned.m16n8k8.row.col.f32.tf32.tf32.f32 "
        "{%0,%1,%2,%3},{%4,%5,%6,%7},{%8,%9},{%0,%1,%2,%3};"
        : "+f"(d0), "+f"(d1), "+f"(d2), "+f"(d3)
        : "r"(a0), "r"(a1), "r"(a2), "r"(a3), "r"(b0), "r"(b1));
}

__global__ __launch_bounds__(128, 4)
void lc2d_kernel(const float* __restrict__ x,
                 const float* __restrict__ w,
                 const float* __restrict__ bias,
                 float* __restrict__ out) {
    extern __shared__ float sm[];
    float* AS = sm;                 // [2][group4][b32][KA]
    float* BS = sm + 2 * ABUF;      // [2][group4][f64][KA]

    const int tid  = threadIdx.x;
    const int or_  = blockIdx.y;
    const int oct0 = blockIdx.x * 4;      // 4 pooled cols per CTA
    const int h0   = or_ * 2;
    const int w0   = oct0 * 2;

    // ---- loader mapping ----
    const int xj   = tid & 1;             // float4 index along 8 input cols
    const int xb   = (tid >> 1) & 31;     // batch
    const int xrow = (tid >> 6) & 1;      // input row within pooled row
    const int wj   = tid & 1;
    const int wf   = (tid >> 1) & 63;     // filter

    const float* xp = x + ((xb * 32) * 128 + h0 + xrow) * 128 + w0 + 4 * xj;
    const float* wp = w + ((wf * 32) * 128 + h0) * 128 + w0 + 4 * wj;

    // STS offsets: global col = 4*j + e ; panel = col>>1 ; cp = col&1
    int a_off[2][4];        // [cc][e]
    int b_off[2][2][4];     // [cc][rw][e]
#pragma unroll
    for (int e = 0; e < 4; ++e) {
        const int pa = 2 * xj + (e >> 1);
        const int pb = 2 * wj + (e >> 1);
#pragma unroll
        for (int cc = 0; cc < 2; ++cc) {
            a_off[cc][e] = pa * AWS + xb * KA + cc * 4 + xrow * 2 + (e & 1);
#pragma unroll
            for (int rw = 0; rw < 2; ++rw)
                b_off[cc][rw][e] = pb * BWS + wf * KA + cc * 4 + rw * 2 + (e & 1);
        }
    }

    // ---- mma mapping: warp = pooled group ----
    const int lane = tid & 31, gp = tid >> 5;
    const int g = lane >> 2, t = lane & 3;

    int a_ld[2][4];
#pragma unroll
    for (int mt = 0; mt < 2; ++mt) {
        a_ld[mt][0] = gp * AWS + (mt * 16 + g)     * KA + t;
        a_ld[mt][1] = gp * AWS + (mt * 16 + g + 8) * KA + t;
        a_ld[mt][2] = a_ld[mt][0] + 4;
        a_ld[mt][3] = a_ld[mt][1] + 4;
    }

    float acc[2][8][4];
#pragma unroll
    for (int mt = 0; mt < 2; ++mt)
#pragma unroll
        for (int nt = 0; nt < 8; ++nt)
#pragma unroll
            for (int r = 0; r < 4; ++r) acc[mt][nt][r] = 0.f;

    float4 xr[2], wr[4];

    auto do_ldg = [&](int stage) {
        const int off = stage * 2 * CSTEP;
#pragma unroll
        for (int cc = 0; cc < 2; ++cc) {
            xr[cc] = *(const float4*)(xp + off + cc * CSTEP);
#pragma unroll
            for (int rw = 0; rw < 2; ++rw)
                wr[cc * 2 + rw] = *(const float4*)(wp + off + cc * CSTEP + rw * 128);
        }
    };
    auto do_sts = [&](int buf) {
        float* An = AS + buf * ABUF;
        float* Bn = BS + buf * BBUF;
#pragma unroll
        for (int cc = 0; cc < 2; ++cc) {
            const float xv[4] = {xr[cc].x, xr[cc].y, xr[cc].z, xr[cc].w};
#pragma unroll
            for (int e = 0; e < 4; ++e)
                An[a_off[cc][e]] = __uint_as_float(f2tf32(xv[e]));
#pragma unroll
            for (int rw = 0; rw < 2; ++rw) {
                const float4 v = wr[cc * 2 + rw];
                const float wv[4] = {v.x, v.y, v.z, v.w};
#pragma unroll
                for (int e = 0; e < 4; ++e)
                    Bn[b_off[cc][rw][e]] = __uint_as_float(f2tf32(wv[e]));
            }
        }
    };

    // ---- prologue: stage0 -> buf0 ; preload stage1 into regs ----
    do_ldg(0);
    do_sts(0);
    do_ldg(1);
    __syncthreads();

    // ---- main loop: 16 stages of 2 channels ----
    for (int s = 0; s < 16; ++s) {
        const int buf = s & 1;

        if (s + 1 < 16) do_sts(buf ^ 1);   // stage s+1 (regs long landed)
        if (s + 2 < 16) do_ldg(s + 2);     // loads for stage s+2

        const float* Ap = AS + buf * ABUF;
        const float* Bp = BS + buf * BBUF + gp * BWS;

        uint32_t a[2][4];
#pragma unroll
        for (int mt = 0; mt < 2; ++mt)
#pragma unroll
            for (int r = 0; r < 4; ++r)
                a[mt][r] = __float_as_uint(Ap[a_ld[mt][r]]);

#pragma unroll
        for (int nt = 0; nt < 8; ++nt) {
            const uint32_t b0 = __float_as_uint(Bp[(nt * 8 + g) * KA + t]);
            const uint32_t b1 = __float_as_uint(Bp[(nt * 8 + g) * KA + t + 4]);
            mma_tf32(acc[0][nt][0], acc[0][nt][1], acc[0][nt][2], acc[0][nt][3],
                     a[0][0], a[0][1], a[0][2], a[0][3], b0, b1);
            mma_tf32(acc[1][nt][0], acc[1][nt][1], acc[1][nt][2], acc[1][nt][3],
                     a[1][0], a[1][1], a[1][2], a[1][3], b0, b1);
        }

        __syncthreads();
    }

    // ---- epilogue: transpose through smem, bias + relu, float4 STG ----
    float* OS = sm;   // safe: last stage ended with __syncthreads()
#pragma unroll
    for (int mt = 0; mt < 2; ++mt)
#pragma unroll
        for (int nt = 0; nt < 8; ++nt) {
            const int r0 = mt * 16 + g;
            const int c0 = nt * 8 + 2 * t;
            OS[r0 * OSM_ROW + c0 * 5 + gp]             = acc[mt][nt][0];
            OS[r0 * OSM_ROW + (c0 + 1) * 5 + gp]       = acc[mt][nt][1];
            OS[(r0 + 8) * OSM_ROW + c0 * 5 + gp]       = acc[mt][nt][2];
            OS[(r0 + 8) * OSM_ROW + (c0 + 1) * 5 + gp] = acc[mt][nt][3];
        }
    __syncthreads();

    const float* bb = bias + or_ * 64 + oct0;   // + f*4096
    float* ob       = out + or_ * 64 + oct0;    // + (b*64+f)*4096
#pragma unroll
    for (int i = 0; i < 16; ++i) {
        const int p  = tid + 128 * i;
        const int b_ = p >> 6;
        const int f_ = p & 63;
        const float4 bv = *(const float4*)(bb + f_ * 4096);
        const float* row = OS + b_ * OSM_ROW + f_ * 5;
        float4 o;
        o.x = fmaxf(row[0] + bv.x, 0.f);
        o.y = fmaxf(row[1] + bv.y, 0.f);
        o.z = fmaxf(row[2] + bv.z, 0.f);
        o.w = fmaxf(row[3] + bv.w, 0.f);
        *(float4*)(ob + (size_t)(b_ * 64 + f_) * 4096) = o;
    }
}

extern "C" void kernel_launch(void* const* d_in, const int* in_sizes, int n_in,
                              void* d_out, int out_size) {
    const float* x    = (const float*)d_in[0];
    const float* w    = (const float*)d_in[1];
    const float* bias = (const float*)d_in[2];
    float* out        = (float*)d_out;

    cudaFuncSetAttribute(lc2d_kernel,
                         cudaFuncAttributeMaxDynamicSharedMemorySize, SMEM_BYTES);

    dim3 grid(16, 64, 1);
    lc2d_kernel<<<grid, 128, SMEM_BYTES>>>(x, w, bias, out);
}

// round 12
// speedup vs baseline: 1.0245x; 1.0245x over previous
#include <cuda_runtime.h>
#include <cstdint>

// ---- A (x) staging: R7-proven padded layout, register double-buffer ----
#define KA 12                 // k-stride (8 + 4 pad)
#define AWS 388               // 32*KA + 4  (warp panel stride, A)
#define ABUF (8*AWS)          // 3104 floats per A buffer
// ---- W ring: cp.async, 4 slots, chunk-preserving padded layout ----
#define WROW 65               // chunks per (c,h,j) row: 64 f + 1 pad
#define WSLOT (16*WROW*4)     // floats per slot: 16 rows * 65 chunks * 4 = 4160
#define WBASE (2*ABUF)        // float offset of W ring (6208)
#define NSLOT 4
#define OSM_ROW 581           // epilogue transpose row stride
#define SMEM_FLOATS (WBASE + NSLOT*WSLOT)   // 6208 + 16640 = 22848
#define SMEM_BYTES (SMEM_FLOATS*4)          // 91392 B  (epilogue needs 74368 <= this)

#define PSTEP (16*32*16384)   // +16 in b dimension (floats)
#define CSTEP 16384           // +1 channel (floats)

__device__ __forceinline__ uint32_t f2tf32(float f) {
    uint32_t u; asm("cvt.rna.tf32.f32 %0, %1;" : "=r"(u) : "f"(f)); return u;
}
__device__ __forceinline__ void mma_tf32(float& d0, float& d1, float& d2, float& d3,
                                         uint32_t a0, uint32_t a1, uint32_t a2, uint32_t a3,
                                         uint32_t b0, uint32_t b1) {
    asm("mma.sync.aligned.m16n8k8.row.col.f32.tf32.tf32.f32 "
        "{%0,%1,%2,%3},{%4,%5,%6,%7},{%8,%9},{%0,%1,%2,%3};"
        : "+f"(d0), "+f"(d1), "+f"(d2), "+f"(d3)
        : "r"(a0), "r"(a1), "r"(a2), "r"(a3), "r"(b0), "r"(b1));
}
__device__ __forceinline__ void cp16(uint32_t dst, const float* src) {
    asm volatile("cp.async.cg.shared.global [%0], [%1], 16;" :: "r"(dst), "l"(src));
}

__global__ __launch_bounds__(256, 2)
void lc2d_kernel(const float* __restrict__ x,
                 const float* __restrict__ w,
                 const float* __restrict__ bias,
                 float* __restrict__ out) {
    extern __shared__ float sm[];
    float* AS = sm;                               // [2][panel8][b32][KA]
    const uint32_t smu = (uint32_t)__cvta_generic_to_shared(sm);

    const int tid  = threadIdx.x;
    const int or_  = blockIdx.y;
    const int oct0 = blockIdx.x * 8;
    const int h0   = or_ * 2;
    const int w0   = oct0 * 2;

    // ---- x loader mapping (R7) ----
    const int colq = tid & 3;
    const int lrow = (tid >> 2) & 1;
    const int lcl  = (tid >> 3) & 1;
    const int lb   = tid >> 4;
    const float* xp = x + ((lb * 32 + lcl) * 128 + h0 + lrow) * 128 + w0 + 4 * colq;

    int a_off[2][4];
#pragma unroll
    for (int e = 0; e < 4; ++e) {
        const int wpe = 2 * colq + (e >> 1);
        const int k   = lcl * 4 + lrow * 2 + (e & 1);
#pragma unroll
        for (int i = 0; i < 2; ++i)
            a_off[i][e] = wpe * AWS + (lb + 16 * i) * KA + k;
    }

    // ---- W loader mapping: 4 cp.async chunks/thread/stage ----
    const int wj = tid & 3;                 // 16B chunk along 16 cols
    const int wf = tid >> 2;                // filter 0..63
    const float* wpg = w + ((wf * 32) * 128 + h0) * 128 + w0 + 4 * wj;
    // chunk row index (c,h,j) -> ((c*2+h)*4 + j) ; dst chunk = row*WROW + wf
    uint32_t w_dst[2][2];                   // [cc][rw] byte addr within slot 0
#pragma unroll
    for (int cc = 0; cc < 2; ++cc)
#pragma unroll
        for (int rw = 0; rw < 2; ++rw)
            w_dst[cc][rw] = smu + (uint32_t)(WBASE * 4) +
                            (uint32_t)((((cc * 2 + rw) * 4 + wj) * WROW + wf) * 16);

    // ---- mma mapping ----
    const int lane = tid & 31, gp = tid >> 5;
    const int g = lane >> 2, t = lane & 3;

    int a_ld[2][4];
#pragma unroll
    for (int mt = 0; mt < 2; ++mt) {
        a_ld[mt][0] = gp * AWS + (mt * 16 + g)     * KA + t;
        a_ld[mt][1] = gp * AWS + (mt * 16 + g + 8) * KA + t;
        a_ld[mt][2] = a_ld[mt][0] + 4;
        a_ld[mt][3] = a_ld[mt][1] + 4;
    }
    // B fragment: k = c*4 + h*2 + cp ; b0 -> c=0 (k=t), b1 -> c=1 (k=t+4)
    // float addr within slot = ((c*2+h)*4 + j)*WROW*4 + f*4 + e
    const int bh  = (t >> 1) & 1, bcp = t & 1;
    const int bj  = (2 * gp + bcp) >> 2;
    const int be  = (2 * gp + bcp) & 3;
    const int boff0 = ((0 + bh) * 4 + bj) * (WROW * 4) + g * 4 + be;   // c=0
    const int boff1 = ((2 + bh) * 4 + bj) * (WROW * 4) + g * 4 + be;   // c=1

    float acc[2][8][4];
#pragma unroll
    for (int mt = 0; mt < 2; ++mt)
#pragma unroll
        for (int nt = 0; nt < 8; ++nt)
#pragma unroll
            for (int r = 0; r < 4; ++r) acc[mt][nt][r] = 0.f;

    float4 xr[2];

    auto ldgA = [&](int stage) {
        const int off = stage * 2 * CSTEP;
#pragma unroll
        for (int i = 0; i < 2; ++i) xr[i] = *(const float4*)(xp + off + i * PSTEP);
    };
    auto stsA = [&](int buf) {
        float* An = AS + buf * ABUF;
#pragma unroll
        for (int i = 0; i < 2; ++i) {
            const float v[4] = {xr[i].x, xr[i].y, xr[i].z, xr[i].w};
#pragma unroll
            for (int e = 0; e < 4; ++e)
                An[a_off[i][e]] = __uint_as_float(f2tf32(v[e]));
        }
    };
    auto issueW = [&](int stage, int slot) {
        const uint32_t so = (uint32_t)(slot * WSLOT * 4);
        const float* src = wpg + stage * 2 * CSTEP;
#pragma unroll
        for (int cc = 0; cc < 2; ++cc)
#pragma unroll
            for (int rw = 0; rw < 2; ++rw)
                cp16(w_dst[cc][rw] + so, src + cc * CSTEP + rw * 128);
    };

    // ---- prologue ----
    ldgA(0);
    stsA(0);
    ldgA(1);
    issueW(0, 0); asm volatile("cp.async.commit_group;");
    issueW(1, 1); asm volatile("cp.async.commit_group;");
    issueW(2, 2); asm volatile("cp.async.commit_group;");
    __syncthreads();

    // ---- main loop: one commit per stage keeps wait_group-2 invariant ----
    for (int s = 0; s < 16; ++s) {
        const int abuf = s & 1;
        const int slot = s & 3;

        asm volatile("cp.async.wait_group 2;");
        __syncthreads();

        if (s + 1 < 16) stsA(abuf ^ 1);     // x stage s+1 (regs long landed)
        if (s + 2 < 16) ldgA(s + 2);        // x loads for stage s+2
        if (s + 3 < 16) issueW(s + 3, (s + 3) & 3);
        asm volatile("cp.async.commit_group;");

        const float* Ap = AS + abuf * ABUF;
        const float* Bp = sm + WBASE + slot * WSLOT;

        uint32_t a[2][4];
#pragma unroll
        for (int mt = 0; mt < 2; ++mt)
#pragma unroll
            for (int r = 0; r < 4; ++r)
                a[mt][r] = __float_as_uint(Ap[a_ld[mt][r]]);

#pragma unroll
        for (int nt = 0; nt < 8; ++nt) {
            const uint32_t b0 = f2tf32(Bp[boff0 + nt * 32]);
            const uint32_t b1 = f2tf32(Bp[boff1 + nt * 32]);
            mma_tf32(acc[0][nt][0], acc[0][nt][1], acc[0][nt][2], acc[0][nt][3],
                     a[0][0], a[0][1], a[0][2], a[0][3], b0, b1);
            mma_tf32(acc[1][nt][0], acc[1][nt][1], acc[1][nt][2], acc[1][nt][3],
                     a[1][0], a[1][1], a[1][2], a[1][3], b0, b1);
        }
    }
    asm volatile("cp.async.wait_group 0;");
    __syncthreads();   // all compute done before smem reuse

    // ---- epilogue: transpose via smem, bias + relu, coalesced STG ----
    float* OS = sm;
#pragma unroll
    for (int mt = 0; mt < 2; ++mt)
#pragma unroll
        for (int nt = 0; nt < 8; ++nt) {
            const int r0 = mt * 16 + g;
            const int c0 = nt * 8 + 2 * t;
            OS[r0 * OSM_ROW + c0 * 9 + gp]             = acc[mt][nt][0];
            OS[r0 * OSM_ROW + (c0 + 1) * 9 + gp]       = acc[mt][nt][1];
            OS[(r0 + 8) * OSM_ROW + c0 * 9 + gp]       = acc[mt][nt][2];
            OS[(r0 + 8) * OSM_ROW + (c0 + 1) * 9 + gp] = acc[mt][nt][3];
        }
    __syncthreads();

    const float* bb = bias + or_ * 64 + oct0;   // + f*4096
    float* ob       = out + or_ * 64 + oct0;    // + (b*64+f)*4096
#pragma unroll
    for (int i = 0; i < 8; ++i) {
        const int p  = tid + 256 * i;
        const int b_ = p >> 6;
        const int f_ = p & 63;
        const float4 bv0 = *(const float4*)(bb + f_ * 4096);
        const float4 bv1 = *(const float4*)(bb + f_ * 4096 + 4);
        const float* row = OS + b_ * OSM_ROW + f_ * 9;
        float4 o0, o1;
        o0.x = fmaxf(row[0] + bv0.x, 0.f);
        o0.y = fmaxf(row[1] + bv0.y, 0.f);
        o0.z = fmaxf(row[2] + bv0.z, 0.f);
        o0.w = fmaxf(row[3] + bv0.w, 0.f);
        o1.x = fmaxf(row[4] + bv1.x, 0.f);
        o1.y = fmaxf(row[5] + bv1.y, 0.f);
        o1.z = fmaxf(row[6] + bv1.z, 0.f);
        o1.w = fmaxf(row[7] + bv1.w, 0.f);
        float4* dst = (float4*)(ob + (size_t)(b_ * 64 + f_) * 4096);
        dst[0] = o0;
        dst[1] = o1;
    }
}

extern "C" void kernel_launch(void* const* d_in, const int* in_sizes, int n_in,
                              void* d_out, int out_size) {
    const float* x    = (const float*)d_in[0];
    const float* w    = (const float*)d_in[1];
    const float* bias = (const float*)d_in[2];
    float* out        = (float*)d_out;

    cudaFuncSetAttribute(lc2d_kernel,
                         cudaFuncAttributeMaxDynamicSharedMemorySize, SMEM_BYTES);

    dim3 grid(8, 64, 1);
    lc2d_kernel<<<grid, 256, SMEM_BYTES>>>(x, w, bias, out);
}